// round 16
// baseline (speedup 1.0000x reference)
#include <cuda_runtime.h>
#include <cuda_bf16.h>
#include <mma.h>
#include <math_constants.h>

using namespace nvcuda;

#define E_ 1024
#define W_ 1024
#define B_ 4
#define H_ 16
#define D_ 64
#define BH_ 64

typedef unsigned long long u64t;
typedef unsigned int u32t;

// ---------------- scratch (symbols only referenced in device code) ----------------
__device__ __nv_bfloat16 g_qkv_hi[12ull * E_ * W_];   // [z=p*4+b][e][w]; p:0=K,1=Q,2=V
__device__ __nv_bfloat16 g_qkv_lo[12ull * E_ * W_];
__device__ __nv_bfloat16 g_w_hi[4ull * E_ * E_];      // [p: K,Q,V,M][e][f]
__device__ __nv_bfloat16 g_w_lo[4ull * E_ * E_];
__device__ __nv_bfloat16 g_x_hi[12ull * E_ * W_];
__device__ __nv_bfloat16 g_x_lo[12ull * E_ * W_];
__device__ __nv_bfloat16 g_o_hi[4ull * E_ * W_];
__device__ __nv_bfloat16 g_o_lo[4ull * E_ * W_];

// ---------------- helpers ----------------
__device__ __forceinline__ u32t smem_u32(const void* p) {
    u32t a;
    asm("{ .reg .u64 t; cvta.to.shared.u64 t, %1; cvt.u32.u64 %0, t; }" : "=r"(a) : "l"(p));
    return a;
}
__device__ __forceinline__ void cp16(u32t dst, const void* src) {
    asm volatile("cp.async.cg.shared.global [%0], [%1], 16;" :: "r"(dst), "l"(src));
}
__device__ __forceinline__ void cp_commit() { asm volatile("cp.async.commit_group;" ::: "memory"); }
__device__ __forceinline__ void cp_wait1()  { asm volatile("cp.async.wait_group 1;" ::: "memory"); }
__device__ __forceinline__ void cp_wait0()  { asm volatile("cp.async.wait_group 0;" ::: "memory"); }

__device__ __forceinline__ void split4(float4 v, uint2& uh, uint2& ul)
{
    __nv_bfloat16 h0 = __float2bfloat16_rn(v.x);
    __nv_bfloat16 h1 = __float2bfloat16_rn(v.y);
    __nv_bfloat16 h2 = __float2bfloat16_rn(v.z);
    __nv_bfloat16 h3 = __float2bfloat16_rn(v.w);
    __nv_bfloat16 l0 = __float2bfloat16_rn(v.x - __bfloat162float(h0));
    __nv_bfloat16 l1 = __float2bfloat16_rn(v.y - __bfloat162float(h1));
    __nv_bfloat16 l2 = __float2bfloat16_rn(v.z - __bfloat162float(h2));
    __nv_bfloat16 l3 = __float2bfloat16_rn(v.w - __bfloat162float(h3));
    uh.x = (u32t)__bfloat16_as_ushort(h0) | ((u32t)__bfloat16_as_ushort(h1) << 16);
    uh.y = (u32t)__bfloat16_as_ushort(h2) | ((u32t)__bfloat16_as_ushort(h3) << 16);
    ul.x = (u32t)__bfloat16_as_ushort(l0) | ((u32t)__bfloat16_as_ushort(l1) << 16);
    ul.y = (u32t)__bfloat16_as_ushort(l2) | ((u32t)__bfloat16_as_ushort(l3) << 16);
}

// one launch: blocks [0,4096) -> weights K,Q,V,M; blocks [4096,16384) -> x
__global__ __launch_bounds__(256) void k_split_all(
    const float* __restrict__ LQ, const float* __restrict__ LK,
    const float* __restrict__ LV, const float* __restrict__ Mw,
    const float* __restrict__ x)
{
    int bid = blockIdx.x;
    if (bid < 4096) {
        int p = bid >> 10;                 // 0=K,1=Q,2=V,3=M
        const float* s = (p == 0) ? LK : (p == 1) ? LQ : (p == 2) ? LV : Mw;
        size_t i = ((size_t)(bid & 1023) * 256 + threadIdx.x) * 4;
        uint2 uh, ul;
        split4(*(const float4*)(s + i), uh, ul);
        size_t o = (size_t)p * E_ * E_ + i;
        *(uint2*)(g_w_hi + o) = uh;
        *(uint2*)(g_w_lo + o) = ul;
    } else {
        size_t i = ((size_t)(bid - 4096) * 256 + threadIdx.x) * 4;
        uint2 uh, ul;
        split4(*(const float4*)(x + i), uh, ul);
        *(uint2*)(g_x_hi + i) = uh;
        *(uint2*)(g_x_lo + i) = ul;
    }
}

// ---------------- wmma typedefs ----------------
typedef wmma::fragment<wmma::matrix_a, 16, 16, 16, __nv_bfloat16, wmma::row_major> FragA;
typedef wmma::fragment<wmma::matrix_a, 16, 16, 16, __nv_bfloat16, wmma::col_major> FragAT;
typedef wmma::fragment<wmma::matrix_b, 16, 16, 16, __nv_bfloat16, wmma::row_major> FragB;
typedef wmma::fragment<wmma::accumulator, 16, 16, 16, float> FragC;

// ---------------- wmma bf16 3-term GEMM, 64x128 tile, cp.async db, 3 CTAs/SM ----------------
#define AK 40
#define BN 136
#define A_BUF 2560             // 64*40 elems per buffer
#define B_BUF 4352             // 32*136
#define OFF_AL_B 10240         // byte offsets (2 bufs * A_BUF * 2B)
#define OFF_BH_B 20480
#define OFF_BL_B 37888
#define SMEM_MMA 55296

__device__ __forceinline__ void mma_gemm_body(
    const __nv_bfloat16* __restrict__ Ah, const __nv_bfloat16* __restrict__ Al,
    const __nv_bfloat16* __restrict__ Bh, const __nv_bfloat16* __restrict__ Bl,
    float* __restrict__ Cf, __nv_bfloat16* __restrict__ Ch, __nv_bfloat16* __restrict__ Cl,
    const float* __restrict__ bias)
{
    extern __shared__ __align__(128) char smem[];
    __nv_bfloat16* sAh = (__nv_bfloat16*)(smem);
    __nv_bfloat16* sAl = (__nv_bfloat16*)(smem + OFF_AL_B);
    __nv_bfloat16* sBh = (__nv_bfloat16*)(smem + OFF_BH_B);
    __nv_bfloat16* sBl = (__nv_bfloat16*)(smem + OFF_BL_B);
    float* stage = (float*)smem;                 // 64*132*4 = 33792 B, reused after compute

    const u32t uAh = smem_u32(sAh);
    const u32t uAl = smem_u32(sAl);
    const u32t uBh = smem_u32(sBh);
    const u32t uBl = smem_u32(sBl);

    const int tid = threadIdx.x;
    const int w = tid >> 5;
    const int wm = w & 1;                        // 2 warps along m
    const int wn = w >> 1;                       // 4 warps along n
    const int m0 = blockIdx.y * 64;
    const int n0 = blockIdx.x * 128;

    const int ar = tid >> 2, ak = (tid & 3) * 8; // A: 64 rows x 32 k, 8 elems/thread
    const int bk = tid >> 3, bn = (tid & 7) * 16;// B: 32 k x 128 n, 16 elems/thread

    const __nv_bfloat16* gAh = Ah + (size_t)(m0 + ar) * 1024 + ak;
    const __nv_bfloat16* gAl = Al + (size_t)(m0 + ar) * 1024 + ak;
    const __nv_bfloat16* gBh = Bh + (size_t)bk * 1024 + n0 + bn;
    const __nv_bfloat16* gBl = Bl + (size_t)bk * 1024 + n0 + bn;

    const u32t aDst = (u32t)((ar * AK + ak) * 2);
    const u32t bDst = (u32t)((bk * BN + bn) * 2);

    FragC acc[2][2];
#pragma unroll
    for (int mi = 0; mi < 2; mi++)
#pragma unroll
        for (int ni = 0; ni < 2; ni++) wmma::fill_fragment(acc[mi][ni], 0.0f);

    {
        cp16(uAh + aDst, gAh);
        cp16(uAl + aDst, gAl);
        cp16(uBh + bDst,      gBh);
        cp16(uBh + bDst + 16, gBh + 8);
        cp16(uBl + bDst,      gBl);
        cp16(uBl + bDst + 16, gBl + 8);
        cp_commit();
    }

    int buf = 0;
    for (int kt = 0; kt < 1024; kt += 32) {
        const bool has = (kt + 32 < 1024);
        if (has) {
            const int nxt = kt + 32;
            const u32t ao = (u32t)((buf ^ 1) * A_BUF * 2);
            const u32t bo = (u32t)((buf ^ 1) * B_BUF * 2);
            cp16(uAh + ao + aDst, gAh + nxt);
            cp16(uAl + ao + aDst, gAl + nxt);
            cp16(uBh + bo + bDst,      gBh + (size_t)nxt * 1024);
            cp16(uBh + bo + bDst + 16, gBh + (size_t)nxt * 1024 + 8);
            cp16(uBl + bo + bDst,      gBl + (size_t)nxt * 1024);
            cp16(uBl + bo + bDst + 16, gBl + (size_t)nxt * 1024 + 8);
            cp_commit();
            cp_wait1();
        } else {
            cp_wait0();
        }
        __syncthreads();

        const int ab = buf * A_BUF, bb = buf * B_BUF;
#pragma unroll
        for (int kk = 0; kk < 32; kk += 16) {
            FragA fah[2], fal[2];
#pragma unroll
            for (int mi = 0; mi < 2; mi++) {
                wmma::load_matrix_sync(fah[mi], &sAh[ab + (wm * 32 + mi * 16) * AK + kk], AK);
                wmma::load_matrix_sync(fal[mi], &sAl[ab + (wm * 32 + mi * 16) * AK + kk], AK);
            }
#pragma unroll
            for (int ni = 0; ni < 2; ni++) {
                FragB fbh, fbl;
                wmma::load_matrix_sync(fbh, &sBh[bb + kk * BN + wn * 32 + ni * 16], BN);
                wmma::load_matrix_sync(fbl, &sBl[bb + kk * BN + wn * 32 + ni * 16], BN);
#pragma unroll
                for (int mi = 0; mi < 2; mi++) {
                    wmma::mma_sync(acc[mi][ni], fah[mi], fbh, acc[mi][ni]);
                    wmma::mma_sync(acc[mi][ni], fah[mi], fbl, acc[mi][ni]);
                    wmma::mma_sync(acc[mi][ni], fal[mi], fbh, acc[mi][ni]);
                }
            }
        }
        __syncthreads();
        buf ^= 1;
    }

#pragma unroll
    for (int mi = 0; mi < 2; mi++)
#pragma unroll
        for (int ni = 0; ni < 2; ni++)
            wmma::store_matrix_sync(&stage[(wm * 32 + mi * 16) * 132 + wn * 32 + ni * 16],
                                    acc[mi][ni], 132, wmma::mem_row_major);
    __syncthreads();

    {
        const int r = tid >> 2;                  // 0..63
        const int cb = (tid & 3) * 32;           // 32 cols per thread
        const float* src = stage + r * 132 + cb;
        if (Cf) {
            const float bv = bias ? bias[m0 + r] : 0.f;
            float* dst = Cf + (size_t)(m0 + r) * 1024 + n0 + cb;
#pragma unroll
            for (int j = 0; j < 8; j++) {
                float4 v = *(const float4*)(src + j * 4);
                v.x += bv; v.y += bv; v.z += bv; v.w += bv;
                *(float4*)(dst + j * 4) = v;
            }
        } else {
            size_t o = (size_t)(m0 + r) * 1024 + n0 + cb;
#pragma unroll
            for (int j = 0; j < 8; j++) {
                uint2 uh, ul;
                split4(*(const float4*)(src + j * 4), uh, ul);
                *(uint2*)(Ch + o + j * 4) = uh;
                *(uint2*)(Cl + o + j * 4) = ul;
            }
        }
    }
}

__global__ __launch_bounds__(256, 3) void k_proj_mma()
{
    int z = blockIdx.z;
    int p = z >> 2;   // 0=K,1=Q,2=V
    mma_gemm_body(g_w_hi + (size_t)p * E_ * E_, g_w_lo + (size_t)p * E_ * E_,
                  g_x_hi + (size_t)z * E_ * W_, g_x_lo + (size_t)z * E_ * W_,
                  nullptr, g_qkv_hi + (size_t)z * E_ * W_, g_qkv_lo + (size_t)z * E_ * W_,
                  nullptr);
}

__global__ __launch_bounds__(256, 3) void k_final_mma(
    const float* __restrict__ bias, float* __restrict__ out)
{
    int b = blockIdx.z;
    mma_gemm_body(g_w_hi + 3ull * E_ * E_, g_w_lo + 3ull * E_ * E_,
                  g_o_hi + (size_t)b * E_ * W_, g_o_lo + (size_t)b * E_ * W_,
                  out + (size_t)b * E_ * W_, nullptr, nullptr, bias);
}

// ---------------- fused attention: single pass, 512 threads, cp.async Q, diag skip ----------------
#define FZ_LD 136
#define OFS_KH 0
#define OFS_KL 17408
#define OFS_QH 34816
#define OFS_QL 52224
#define OFS_PH 34816
#define OFS_PL 69632
#define OFS_S  104448
#define OFS_VH 172032
#define OFS_VL 189440
#define OFS_M  206848
#define OFS_L  207360
#define OFS_PART 207872
#define SMEM_FZ 211968          // PART [8][128] fp32

__global__ __launch_bounds__(512) void k_attn_fused()
{
    extern __shared__ __align__(128) char smem[];
    __nv_bfloat16* sKh = (__nv_bfloat16*)(smem + OFS_KH);
    __nv_bfloat16* sKl = (__nv_bfloat16*)(smem + OFS_KL);
    __nv_bfloat16* sQh = (__nv_bfloat16*)(smem + OFS_QH);
    __nv_bfloat16* sQl = (__nv_bfloat16*)(smem + OFS_QL);
    __nv_bfloat16* sPh = (__nv_bfloat16*)(smem + OFS_PH);   // overlays Q region
    __nv_bfloat16* sPl = (__nv_bfloat16*)(smem + OFS_PL);
    float* sS = (float*)(smem + OFS_S);                      // [128][132]
    __nv_bfloat16* sVh = (__nv_bfloat16*)(smem + OFS_VH);
    __nv_bfloat16* sVl = (__nv_bfloat16*)(smem + OFS_VL);
    float* sM = (float*)(smem + OFS_M);
    float* sL = (float*)(smem + OFS_L);
    float* sPart = (float*)(smem + OFS_PART);                // [8][128]

    const int kt = 7 - blockIdx.x;
    const int n0 = kt * 128;
    const int z = blockIdx.y;
    const int b = z >> 4, h = z & 15;
    const size_t qoff = (size_t)((4 + b) * E_ + h * D_) * W_;
    const size_t koff = (size_t)(b * E_ + h * D_) * W_;
    const size_t voff = (size_t)((8 + b) * E_ + h * D_) * W_;

    const int tid = threadIdx.x;
    const int w = tid >> 5;

    const int lrow = tid >> 3;              // 0..63 (d rows)
    const int lcb  = (tid & 7) * 16;        // 16 cols per thread

    const u32t uQh = smem_u32(sQh);
    const u32t uQl = smem_u32(sQl);
    const u32t qDst = (u32t)((lrow * FZ_LD + lcb) * 2);

    // K tile (persistent)
#pragma unroll
    for (int u = 0; u < 2; u++) {
        int col = lcb + u * 8;
        *(uint4*)(&sKh[lrow * FZ_LD + col]) = *(const uint4*)(g_qkv_hi + koff + (size_t)lrow * W_ + n0 + col);
        *(uint4*)(&sKl[lrow * FZ_LD + col]) = *(const uint4*)(g_qkv_lo + koff + (size_t)lrow * W_ + n0 + col);
    }
    if (tid < 128) sL[tid] = 0.f;

    const int cp = (tid & 63) * 2;          // owns cols cp, cp+1
    const int rq = tid >> 6;                // 0..7, rows rq*16..rq*16+15

    const int swm = w & 3, swn = w >> 2;    // scores: 4x4 warp grid (32x32)
    const int awm = w & 1, awn = w >> 1;    // AV: 2x8 warp grid (32x16)

    FragC oacc[2];
#pragma unroll
    for (int mi = 0; mi < 2; mi++) wmma::fill_fragment(oacc[mi], 0.0f);

    for (int t = 0; t <= kt; t++) {
        __syncthreads();   // previous AV reads of P/V done (P overlays Q region)
        {
            const __nv_bfloat16* gq_h = g_qkv_hi + qoff + (size_t)lrow * W_ + t * 128 + lcb;
            const __nv_bfloat16* gq_l = g_qkv_lo + qoff + (size_t)lrow * W_ + t * 128 + lcb;
            cp16(uQh + qDst,      gq_h);
            cp16(uQh + qDst + 16, gq_h + 8);
            cp16(uQl + qDst,      gq_l);
            cp16(uQl + qDst + 16, gq_l + 8);
            cp_commit();
        }
        uint4 vh[2], vl[2];
#pragma unroll
        for (int u = 0; u < 2; u++) {
            int col = lcb + u * 8;
            vh[u] = *(const uint4*)(g_qkv_hi + voff + (size_t)lrow * W_ + t * 128 + col);
            vl[u] = *(const uint4*)(g_qkv_lo + voff + (size_t)lrow * W_ + t * 128 + col);
        }
        cp_wait0();
        __syncthreads();

        // S = Q^T K (3-term), 32x32 per warp; skip fully-masked diag warp tiles
        const bool diag = (t == kt);
        if (!diag || swm <= swn) {
            FragC sacc[2][2];
#pragma unroll
            for (int mi = 0; mi < 2; mi++)
#pragma unroll
                for (int ni = 0; ni < 2; ni++) wmma::fill_fragment(sacc[mi][ni], 0.0f);
#pragma unroll
            for (int ks = 0; ks < 64; ks += 16) {
                FragAT fah[2], fal[2];
#pragma unroll
                for (int mi = 0; mi < 2; mi++) {
                    wmma::load_matrix_sync(fah[mi], &sQh[ks * FZ_LD + swm * 32 + mi * 16], FZ_LD);
                    wmma::load_matrix_sync(fal[mi], &sQl[ks * FZ_LD + swm * 32 + mi * 16], FZ_LD);
                }
#pragma unroll
                for (int ni = 0; ni < 2; ni++) {
                    FragB fbh, fbl;
                    wmma::load_matrix_sync(fbh, &sKh[ks * FZ_LD + swn * 32 + ni * 16], FZ_LD);
                    wmma::load_matrix_sync(fbl, &sKl[ks * FZ_LD + swn * 32 + ni * 16], FZ_LD);
#pragma unroll
                    for (int mi = 0; mi < 2; mi++) {
                        wmma::mma_sync(sacc[mi][ni], fah[mi], fbh, sacc[mi][ni]);
                        wmma::mma_sync(sacc[mi][ni], fah[mi], fbl, sacc[mi][ni]);
                        wmma::mma_sync(sacc[mi][ni], fal[mi], fbh, sacc[mi][ni]);
                    }
                }
            }
#pragma unroll
            for (int mi = 0; mi < 2; mi++)
#pragma unroll
                for (int ni = 0; ni < 2; ni++)
                    wmma::store_matrix_sync(&sS[(swm * 32 + mi * 16) * 132 + swn * 32 + ni * 16],
                                            sacc[mi][ni], 132, wmma::mem_row_major);
        }
        __syncthreads();

        // P = exp(S); 16 rows x 2 cols per thread; V regs -> smem
        float l0 = 0.f, l1 = 0.f;
        for (int r = 0; r < 16; r++) {
            int ql = rq * 16 + r;
            float2 v = *(const float2*)(&sS[ql * 132 + cp]);
            float p0 = (!diag || ql <= cp)     ? __expf(v.x) : 0.f;
            float p1 = (!diag || ql <= cp + 1) ? __expf(v.y) : 0.f;
            l0 += p0; l1 += p1;
            __nv_bfloat16 h0 = __float2bfloat16_rn(p0);
            __nv_bfloat16 h1 = __float2bfloat16_rn(p1);
            __nv_bfloat16 g0 = __float2bfloat16_rn(p0 - __bfloat162float(h0));
            __nv_bfloat16 g1 = __float2bfloat16_rn(p1 - __bfloat162float(h1));
            *(u32t*)(&sPh[ql * FZ_LD + cp]) = (u32t)__bfloat16_as_ushort(h0) | ((u32t)__bfloat16_as_ushort(h1) << 16);
            *(u32t*)(&sPl[ql * FZ_LD + cp]) = (u32t)__bfloat16_as_ushort(g0) | ((u32t)__bfloat16_as_ushort(g1) << 16);
        }
#pragma unroll
        for (int u = 0; u < 2; u++) {
            int col = lcb + u * 8;
            *(uint4*)(&sVh[lrow * FZ_LD + col]) = vh[u];
            *(uint4*)(&sVl[lrow * FZ_LD + col]) = vl[u];
        }
        sPart[rq * 128 + cp]     = l0;
        sPart[rq * 128 + cp + 1] = l1;
        __syncthreads();
        if (tid < 128) {
            float s = 0.f;
#pragma unroll
            for (int i = 0; i < 8; i++) s += sPart[i * 128 + tid];
            sL[tid] += s;
        }

        // O += V @ P (3-term), 32x16 per warp
#pragma unroll
        for (int ks = 0; ks < 128; ks += 16) {
            FragA fvh[2], fvl[2];
#pragma unroll
            for (int mi = 0; mi < 2; mi++) {
                wmma::load_matrix_sync(fvh[mi], &sVh[(awm * 32 + mi * 16) * FZ_LD + ks], FZ_LD);
                wmma::load_matrix_sync(fvl[mi], &sVl[(awm * 32 + mi * 16) * FZ_LD + ks], FZ_LD);
            }
            FragB fph, fpl;
            wmma::load_matrix_sync(fph, &sPh[ks * FZ_LD + awn * 16], FZ_LD);
            wmma::load_matrix_sync(fpl, &sPl[ks * FZ_LD + awn * 16], FZ_LD);
#pragma unroll
            for (int mi = 0; mi < 2; mi++) {
                wmma::mma_sync(oacc[mi], fvh[mi], fph, oacc[mi]);
                wmma::mma_sync(oacc[mi], fvh[mi], fpl, oacc[mi]);
                wmma::mma_sync(oacc[mi], fvl[mi], fph, oacc[mi]);
            }
        }
    }
    __syncthreads();

    // epilogue
#pragma unroll
    for (int mi = 0; mi < 2; mi++)
        wmma::store_matrix_sync(&sS[(awm * 32 + mi * 16) * 132 + awn * 16],
                                oacc[mi], 132, wmma::mem_row_major);
    if (tid < 128) sM[tid] = 1.0f / (32.0f * sL[tid]);
    __syncthreads();

    {
        const size_t obase = (size_t)(b * E_ + h * D_ + lrow) * W_ + n0;
#pragma unroll
        for (int u = 0; u < 4; u++) {
            int col = lcb + u * 4;
            float4 v = *(const float4*)(&sS[lrow * 132 + col]);
            v.x *= sM[col]; v.y *= sM[col + 1]; v.z *= sM[col + 2]; v.w *= sM[col + 3];
            uint2 uh, ul;
            split4(v, uh, ul);
            *(uint2*)(g_o_hi + obase + col) = uh;
            *(uint2*)(g_o_lo + obase + col) = ul;
        }
    }
}

// ---------------------------------------------------------------------------
extern "C" void kernel_launch(void* const* d_in, const int* in_sizes, int n_in,
                              void* d_out, int out_size)
{
    const float* x  = (const float*)d_in[0];
    const float* LQ = (const float*)d_in[1];
    const float* LK = (const float*)d_in[2];
    const float* LV = (const float*)d_in[3];
    const float* Mw = (const float*)d_in[4];
    const float* bv = (const float*)d_in[5];
    float* out = (float*)d_out;

    cudaFuncSetAttribute(k_proj_mma,   cudaFuncAttributeMaxDynamicSharedMemorySize, SMEM_MMA);
    cudaFuncSetAttribute(k_final_mma,  cudaFuncAttributeMaxDynamicSharedMemorySize, SMEM_MMA);
    cudaFuncSetAttribute(k_attn_fused, cudaFuncAttributeMaxDynamicSharedMemorySize, SMEM_FZ);

    dim3 blk(256);

    k_split_all<<<16384, blk>>>(LQ, LK, LV, Mw, x);

    k_proj_mma  <<<dim3(8, 16, 12), blk, SMEM_MMA>>>();
    k_attn_fused<<<dim3(8, 64),     512, SMEM_FZ>>>();
    k_final_mma <<<dim3(8, 16, 4),  blk, SMEM_MMA>>>(bv, out);
}

// round 17
// speedup vs baseline: 1.0507x; 1.0507x over previous
#include <cuda_runtime.h>
#include <cuda_bf16.h>
#include <mma.h>
#include <math_constants.h>

using namespace nvcuda;

#define E_ 1024
#define W_ 1024
#define B_ 4
#define H_ 16
#define D_ 64
#define BH_ 64

typedef unsigned long long u64t;
typedef unsigned int u32t;

// ---------------- scratch (symbols only referenced in device code) ----------------
__device__ __nv_bfloat16 g_qkv_hi[12ull * E_ * W_];   // [z=p*4+b][e][w]; p:0=K,1=Q,2=V
__device__ __nv_bfloat16 g_qkv_lo[12ull * E_ * W_];
__device__ __nv_bfloat16 g_w_hi[4ull * E_ * E_];      // [p: K,Q,V,M][e][f]
__device__ __nv_bfloat16 g_w_lo[4ull * E_ * E_];
__device__ __nv_bfloat16 g_x_hi[12ull * E_ * W_];
__device__ __nv_bfloat16 g_x_lo[12ull * E_ * W_];
__device__ __nv_bfloat16 g_o_hi[4ull * E_ * W_];
__device__ __nv_bfloat16 g_o_lo[4ull * E_ * W_];

// ---------------- helpers ----------------
__device__ __forceinline__ u32t smem_u32(const void* p) {
    u32t a;
    asm("{ .reg .u64 t; cvta.to.shared.u64 t, %1; cvt.u32.u64 %0, t; }" : "=r"(a) : "l"(p));
    return a;
}
__device__ __forceinline__ void cp16(u32t dst, const void* src) {
    asm volatile("cp.async.cg.shared.global [%0], [%1], 16;" :: "r"(dst), "l"(src));
}
__device__ __forceinline__ void cp_commit() { asm volatile("cp.async.commit_group;" ::: "memory"); }
__device__ __forceinline__ void cp_wait1()  { asm volatile("cp.async.wait_group 1;" ::: "memory"); }
__device__ __forceinline__ void cp_wait0()  { asm volatile("cp.async.wait_group 0;" ::: "memory"); }

__device__ __forceinline__ void split4(float4 v, uint2& uh, uint2& ul)
{
    __nv_bfloat16 h0 = __float2bfloat16_rn(v.x);
    __nv_bfloat16 h1 = __float2bfloat16_rn(v.y);
    __nv_bfloat16 h2 = __float2bfloat16_rn(v.z);
    __nv_bfloat16 h3 = __float2bfloat16_rn(v.w);
    __nv_bfloat16 l0 = __float2bfloat16_rn(v.x - __bfloat162float(h0));
    __nv_bfloat16 l1 = __float2bfloat16_rn(v.y - __bfloat162float(h1));
    __nv_bfloat16 l2 = __float2bfloat16_rn(v.z - __bfloat162float(h2));
    __nv_bfloat16 l3 = __float2bfloat16_rn(v.w - __bfloat162float(h3));
    uh.x = (u32t)__bfloat16_as_ushort(h0) | ((u32t)__bfloat16_as_ushort(h1) << 16);
    uh.y = (u32t)__bfloat16_as_ushort(h2) | ((u32t)__bfloat16_as_ushort(h3) << 16);
    ul.x = (u32t)__bfloat16_as_ushort(l0) | ((u32t)__bfloat16_as_ushort(l1) << 16);
    ul.y = (u32t)__bfloat16_as_ushort(l2) | ((u32t)__bfloat16_as_ushort(l3) << 16);
}

// one launch: blocks [0,4096) -> weights K,Q,V,M; blocks [4096,16384) -> x
__global__ __launch_bounds__(256) void k_split_all(
    const float* __restrict__ LQ, const float* __restrict__ LK,
    const float* __restrict__ LV, const float* __restrict__ Mw,
    const float* __restrict__ x)
{
    int bid = blockIdx.x;
    if (bid < 4096) {
        int p = bid >> 10;                 // 0=K,1=Q,2=V,3=M
        const float* s = (p == 0) ? LK : (p == 1) ? LQ : (p == 2) ? LV : Mw;
        size_t i = ((size_t)(bid & 1023) * 256 + threadIdx.x) * 4;
        uint2 uh, ul;
        split4(*(const float4*)(s + i), uh, ul);
        size_t o = (size_t)p * E_ * E_ + i;
        *(uint2*)(g_w_hi + o) = uh;
        *(uint2*)(g_w_lo + o) = ul;
    } else {
        size_t i = ((size_t)(bid - 4096) * 256 + threadIdx.x) * 4;
        uint2 uh, ul;
        split4(*(const float4*)(x + i), uh, ul);
        *(uint2*)(g_x_hi + i) = uh;
        *(uint2*)(g_x_lo + i) = ul;
    }
}

// ---------------- wmma typedefs ----------------
typedef wmma::fragment<wmma::matrix_a, 16, 16, 16, __nv_bfloat16, wmma::row_major> FragA;
typedef wmma::fragment<wmma::matrix_a, 16, 16, 16, __nv_bfloat16, wmma::col_major> FragAT;
typedef wmma::fragment<wmma::matrix_b, 16, 16, 16, __nv_bfloat16, wmma::row_major> FragB;
typedef wmma::fragment<wmma::accumulator, 16, 16, 16, float> FragC;

// ---------------- wmma bf16 3-term GEMM, 128x128 tile, 3-stage cp.async, 1 sync/iter ----------------
#define AK 40
#define BN 136
// per-stage byte layout: AH[0,10240) AL[10240,20480) BH[20480,29184) BL[29184,37888)
#define STG_B   37888
#define S_AH    0
#define S_AL    10240
#define S_BH    20480
#define S_BL    29184
#define SMEM_MMA (3 * STG_B)      // 113664

__device__ __forceinline__ void mma_gemm_body(
    const __nv_bfloat16* __restrict__ Ah, const __nv_bfloat16* __restrict__ Al,
    const __nv_bfloat16* __restrict__ Bh, const __nv_bfloat16* __restrict__ Bl,
    float* __restrict__ Cf, __nv_bfloat16* __restrict__ Ch, __nv_bfloat16* __restrict__ Cl,
    const float* __restrict__ bias)
{
    extern __shared__ __align__(128) char smem[];
    float* stage = (float*)smem;              // epilogue staging overlays stages 0..1

    const u32t uS = smem_u32(smem);

    const int tid = threadIdx.x;
    const int w = tid >> 5;
    const int wm = w & 3;                     // 4 warps along m
    const int wn = w >> 2;                    // 2 warps along n
    const int m0 = blockIdx.y * 128;
    const int n0 = blockIdx.x * 128;

    const int ar = tid >> 1, ak = (tid & 1) * 16;   // A: 128 rows x 32 k
    const int bk = tid >> 3, bn = (tid & 7) * 16;   // B: 32 k x 128 n

    const __nv_bfloat16* gAh = Ah + (size_t)(m0 + ar) * 1024 + ak;
    const __nv_bfloat16* gAl = Al + (size_t)(m0 + ar) * 1024 + ak;
    const __nv_bfloat16* gBh = Bh + (size_t)bk * 1024 + n0 + bn;
    const __nv_bfloat16* gBl = Bl + (size_t)bk * 1024 + n0 + bn;

    const u32t aOfs = (u32t)((ar * AK + ak) * 2);
    const u32t bOfs = (u32t)((bk * BN + bn) * 2);

    FragC acc[2][4];
#pragma unroll
    for (int mi = 0; mi < 2; mi++)
#pragma unroll
        for (int ni = 0; ni < 4; ni++) wmma::fill_fragment(acc[mi][ni], 0.0f);

    // issue helper (macro-ish lambda)
    auto issue = [&](int s, int kt) {
        const u32t base = uS + (u32t)s * STG_B;
        cp16(base + S_AH + aOfs,      gAh + kt);
        cp16(base + S_AH + aOfs + 16, gAh + kt + 8);
        cp16(base + S_AL + aOfs,      gAl + kt);
        cp16(base + S_AL + aOfs + 16, gAl + kt + 8);
        cp16(base + S_BH + bOfs,      gBh + (size_t)kt * 1024);
        cp16(base + S_BH + bOfs + 16, gBh + (size_t)kt * 1024 + 8);
        cp16(base + S_BL + bOfs,      gBl + (size_t)kt * 1024);
        cp16(base + S_BL + bOfs + 16, gBl + (size_t)kt * 1024 + 8);
        cp_commit();
    };

    issue(0, 0);
    issue(1, 32);

    const int NIT = 32;   // 1024 / 32
    for (int i = 0; i < NIT; i++) {
        if (i < NIT - 1) cp_wait1(); else cp_wait0();
        __syncthreads();

        const int s = i % 3;
        const __nv_bfloat16* cAh = (const __nv_bfloat16*)(smem + s * STG_B + S_AH);
        const __nv_bfloat16* cAl = (const __nv_bfloat16*)(smem + s * STG_B + S_AL);
        const __nv_bfloat16* cBh = (const __nv_bfloat16*)(smem + s * STG_B + S_BH);
        const __nv_bfloat16* cBl = (const __nv_bfloat16*)(smem + s * STG_B + S_BL);

#pragma unroll
        for (int kk = 0; kk < 32; kk += 16) {
            FragA fah[2], fal[2];
#pragma unroll
            for (int mi = 0; mi < 2; mi++) {
                wmma::load_matrix_sync(fah[mi], &cAh[(wm * 32 + mi * 16) * AK + kk], AK);
                wmma::load_matrix_sync(fal[mi], &cAl[(wm * 32 + mi * 16) * AK + kk], AK);
            }
#pragma unroll
            for (int ni = 0; ni < 4; ni++) {
                FragB fbh, fbl;
                wmma::load_matrix_sync(fbh, &cBh[kk * BN + wn * 64 + ni * 16], BN);
                wmma::load_matrix_sync(fbl, &cBl[kk * BN + wn * 64 + ni * 16], BN);
#pragma unroll
                for (int mi = 0; mi < 2; mi++) {
                    wmma::mma_sync(acc[mi][ni], fah[mi], fbh, acc[mi][ni]);
                    wmma::mma_sync(acc[mi][ni], fah[mi], fbl, acc[mi][ni]);
                    wmma::mma_sync(acc[mi][ni], fal[mi], fbh, acc[mi][ni]);
                }
            }
        }

        if (i + 2 < NIT) issue((i + 2) % 3, (i + 2) * 32);
    }
    __syncthreads();   // all compute done before epilogue staging overwrites stages

#pragma unroll
    for (int mi = 0; mi < 2; mi++)
#pragma unroll
        for (int ni = 0; ni < 4; ni++)
            wmma::store_matrix_sync(&stage[(wm * 32 + mi * 16) * 132 + wn * 64 + ni * 16],
                                    acc[mi][ni], 132, wmma::mem_row_major);
    __syncthreads();

    {
        const int r = tid >> 1;
        const int hf = (tid & 1) * 64;
        const float* src = stage + r * 132 + hf;
        if (Cf) {
            const float bv = bias ? bias[m0 + r] : 0.f;
            float* dst = Cf + (size_t)(m0 + r) * 1024 + n0 + hf;
#pragma unroll
            for (int j = 0; j < 16; j++) {
                float4 v = *(const float4*)(src + j * 4);
                v.x += bv; v.y += bv; v.z += bv; v.w += bv;
                *(float4*)(dst + j * 4) = v;
            }
        } else {
            size_t o = (size_t)(m0 + r) * 1024 + n0 + hf;
#pragma unroll
            for (int j = 0; j < 16; j++) {
                uint2 uh, ul;
                split4(*(const float4*)(src + j * 4), uh, ul);
                *(uint2*)(Ch + o + j * 4) = uh;
                *(uint2*)(Cl + o + j * 4) = ul;
            }
        }
    }
}

__global__ __launch_bounds__(256, 2) void k_proj_mma()
{
    int z = blockIdx.z;
    int p = z >> 2;   // 0=K,1=Q,2=V
    mma_gemm_body(g_w_hi + (size_t)p * E_ * E_, g_w_lo + (size_t)p * E_ * E_,
                  g_x_hi + (size_t)z * E_ * W_, g_x_lo + (size_t)z * E_ * W_,
                  nullptr, g_qkv_hi + (size_t)z * E_ * W_, g_qkv_lo + (size_t)z * E_ * W_,
                  nullptr);
}

__global__ __launch_bounds__(256, 2) void k_final_mma(
    const float* __restrict__ bias, float* __restrict__ out)
{
    int b = blockIdx.z;
    mma_gemm_body(g_w_hi + 3ull * E_ * E_, g_w_lo + 3ull * E_ * E_,
                  g_o_hi + (size_t)b * E_ * W_, g_o_lo + (size_t)b * E_ * W_,
                  out + (size_t)b * E_ * W_, nullptr, nullptr, bias);
}

// ---------------- fused attention: single pass, 512 threads, cp.async Q, diag skip ----------------
#define FZ_LD 136
#define OFS_KH 0
#define OFS_KL 17408
#define OFS_QH 34816
#define OFS_QL 52224
#define OFS_PH 34816
#define OFS_PL 69632
#define OFS_S  104448
#define OFS_VH 172032
#define OFS_VL 189440
#define OFS_M  206848
#define OFS_L  207360
#define OFS_PART 207872
#define SMEM_FZ 211968          // PART [8][128] fp32

__global__ __launch_bounds__(512) void k_attn_fused()
{
    extern __shared__ __align__(128) char smem[];
    __nv_bfloat16* sKh = (__nv_bfloat16*)(smem + OFS_KH);
    __nv_bfloat16* sKl = (__nv_bfloat16*)(smem + OFS_KL);
    __nv_bfloat16* sQh = (__nv_bfloat16*)(smem + OFS_QH);
    __nv_bfloat16* sQl = (__nv_bfloat16*)(smem + OFS_QL);
    __nv_bfloat16* sPh = (__nv_bfloat16*)(smem + OFS_PH);   // overlays Q region
    __nv_bfloat16* sPl = (__nv_bfloat16*)(smem + OFS_PL);
    float* sS = (float*)(smem + OFS_S);                      // [128][132]
    __nv_bfloat16* sVh = (__nv_bfloat16*)(smem + OFS_VH);
    __nv_bfloat16* sVl = (__nv_bfloat16*)(smem + OFS_VL);
    float* sM = (float*)(smem + OFS_M);
    float* sL = (float*)(smem + OFS_L);
    float* sPart = (float*)(smem + OFS_PART);                // [8][128]

    const int kt = 7 - blockIdx.x;
    const int n0 = kt * 128;
    const int z = blockIdx.y;
    const int b = z >> 4, h = z & 15;
    const size_t qoff = (size_t)((4 + b) * E_ + h * D_) * W_;
    const size_t koff = (size_t)(b * E_ + h * D_) * W_;
    const size_t voff = (size_t)((8 + b) * E_ + h * D_) * W_;

    const int tid = threadIdx.x;
    const int w = tid >> 5;

    const int lrow = tid >> 3;              // 0..63 (d rows)
    const int lcb  = (tid & 7) * 16;        // 16 cols per thread

    const u32t uQh = smem_u32(sQh);
    const u32t uQl = smem_u32(sQl);
    const u32t qDst = (u32t)((lrow * FZ_LD + lcb) * 2);

    // K tile (persistent)
#pragma unroll
    for (int u = 0; u < 2; u++) {
        int col = lcb + u * 8;
        *(uint4*)(&sKh[lrow * FZ_LD + col]) = *(const uint4*)(g_qkv_hi + koff + (size_t)lrow * W_ + n0 + col);
        *(uint4*)(&sKl[lrow * FZ_LD + col]) = *(const uint4*)(g_qkv_lo + koff + (size_t)lrow * W_ + n0 + col);
    }
    if (tid < 128) sL[tid] = 0.f;

    const int cp = (tid & 63) * 2;          // owns cols cp, cp+1
    const int rq = tid >> 6;                // 0..7, rows rq*16..rq*16+15

    const int swm = w & 3, swn = w >> 2;    // scores: 4x4 warp grid (32x32)
    const int awm = w & 1, awn = w >> 1;    // AV: 2x8 warp grid (32x16)

    FragC oacc[2];
#pragma unroll
    for (int mi = 0; mi < 2; mi++) wmma::fill_fragment(oacc[mi], 0.0f);

    for (int t = 0; t <= kt; t++) {
        __syncthreads();   // previous AV reads of P/V done (P overlays Q region)
        {
            const __nv_bfloat16* gq_h = g_qkv_hi + qoff + (size_t)lrow * W_ + t * 128 + lcb;
            const __nv_bfloat16* gq_l = g_qkv_lo + qoff + (size_t)lrow * W_ + t * 128 + lcb;
            cp16(uQh + qDst,      gq_h);
            cp16(uQh + qDst + 16, gq_h + 8);
            cp16(uQl + qDst,      gq_l);
            cp16(uQl + qDst + 16, gq_l + 8);
            cp_commit();
        }
        uint4 vh[2], vl[2];
#pragma unroll
        for (int u = 0; u < 2; u++) {
            int col = lcb + u * 8;
            vh[u] = *(const uint4*)(g_qkv_hi + voff + (size_t)lrow * W_ + t * 128 + col);
            vl[u] = *(const uint4*)(g_qkv_lo + voff + (size_t)lrow * W_ + t * 128 + col);
        }
        cp_wait0();
        __syncthreads();

        // S = Q^T K (3-term), 32x32 per warp; skip fully-masked diag warp tiles
        const bool diag = (t == kt);
        if (!diag || swm <= swn) {
            FragC sacc[2][2];
#pragma unroll
            for (int mi = 0; mi < 2; mi++)
#pragma unroll
                for (int ni = 0; ni < 2; ni++) wmma::fill_fragment(sacc[mi][ni], 0.0f);
#pragma unroll
            for (int ks = 0; ks < 64; ks += 16) {
                FragAT fah[2], fal[2];
#pragma unroll
                for (int mi = 0; mi < 2; mi++) {
                    wmma::load_matrix_sync(fah[mi], &sQh[ks * FZ_LD + swm * 32 + mi * 16], FZ_LD);
                    wmma::load_matrix_sync(fal[mi], &sQl[ks * FZ_LD + swm * 32 + mi * 16], FZ_LD);
                }
#pragma unroll
                for (int ni = 0; ni < 2; ni++) {
                    FragB fbh, fbl;
                    wmma::load_matrix_sync(fbh, &sKh[ks * FZ_LD + swn * 32 + ni * 16], FZ_LD);
                    wmma::load_matrix_sync(fbl, &sKl[ks * FZ_LD + swn * 32 + ni * 16], FZ_LD);
#pragma unroll
                    for (int mi = 0; mi < 2; mi++) {
                        wmma::mma_sync(sacc[mi][ni], fah[mi], fbh, sacc[mi][ni]);
                        wmma::mma_sync(sacc[mi][ni], fah[mi], fbl, sacc[mi][ni]);
                        wmma::mma_sync(sacc[mi][ni], fal[mi], fbh, sacc[mi][ni]);
                    }
                }
            }
#pragma unroll
            for (int mi = 0; mi < 2; mi++)
#pragma unroll
                for (int ni = 0; ni < 2; ni++)
                    wmma::store_matrix_sync(&sS[(swm * 32 + mi * 16) * 132 + swn * 32 + ni * 16],
                                            sacc[mi][ni], 132, wmma::mem_row_major);
        }
        __syncthreads();

        // P = exp(S); 16 rows x 2 cols per thread; V regs -> smem
        float l0 = 0.f, l1 = 0.f;
        for (int r = 0; r < 16; r++) {
            int ql = rq * 16 + r;
            float2 v = *(const float2*)(&sS[ql * 132 + cp]);
            float p0 = (!diag || ql <= cp)     ? __expf(v.x) : 0.f;
            float p1 = (!diag || ql <= cp + 1) ? __expf(v.y) : 0.f;
            l0 += p0; l1 += p1;
            __nv_bfloat16 h0 = __float2bfloat16_rn(p0);
            __nv_bfloat16 h1 = __float2bfloat16_rn(p1);
            __nv_bfloat16 g0 = __float2bfloat16_rn(p0 - __bfloat162float(h0));
            __nv_bfloat16 g1 = __float2bfloat16_rn(p1 - __bfloat162float(h1));
            *(u32t*)(&sPh[ql * FZ_LD + cp]) = (u32t)__bfloat16_as_ushort(h0) | ((u32t)__bfloat16_as_ushort(h1) << 16);
            *(u32t*)(&sPl[ql * FZ_LD + cp]) = (u32t)__bfloat16_as_ushort(g0) | ((u32t)__bfloat16_as_ushort(g1) << 16);
        }
#pragma unroll
        for (int u = 0; u < 2; u++) {
            int col = lcb + u * 8;
            *(uint4*)(&sVh[lrow * FZ_LD + col]) = vh[u];
            *(uint4*)(&sVl[lrow * FZ_LD + col]) = vl[u];
        }
        sPart[rq * 128 + cp]     = l0;
        sPart[rq * 128 + cp + 1] = l1;
        __syncthreads();
        if (tid < 128) {
            float s = 0.f;
#pragma unroll
            for (int i = 0; i < 8; i++) s += sPart[i * 128 + tid];
            sL[tid] += s;
        }

        // O += V @ P (3-term), 32x16 per warp
#pragma unroll
        for (int ks = 0; ks < 128; ks += 16) {
            FragA fvh[2], fvl[2];
#pragma unroll
            for (int mi = 0; mi < 2; mi++) {
                wmma::load_matrix_sync(fvh[mi], &sVh[(awm * 32 + mi * 16) * FZ_LD + ks], FZ_LD);
                wmma::load_matrix_sync(fvl[mi], &sVl[(awm * 32 + mi * 16) * FZ_LD + ks], FZ_LD);
            }
            FragB fph, fpl;
            wmma::load_matrix_sync(fph, &sPh[ks * FZ_LD + awn * 16], FZ_LD);
            wmma::load_matrix_sync(fpl, &sPl[ks * FZ_LD + awn * 16], FZ_LD);
#pragma unroll
            for (int mi = 0; mi < 2; mi++) {
                wmma::mma_sync(oacc[mi], fvh[mi], fph, oacc[mi]);
                wmma::mma_sync(oacc[mi], fvh[mi], fpl, oacc[mi]);
                wmma::mma_sync(oacc[mi], fvl[mi], fph, oacc[mi]);
            }
        }
    }
    __syncthreads();

    // epilogue
#pragma unroll
    for (int mi = 0; mi < 2; mi++)
        wmma::store_matrix_sync(&sS[(awm * 32 + mi * 16) * 132 + awn * 16],
                                oacc[mi], 132, wmma::mem_row_major);
    if (tid < 128) sM[tid] = 1.0f / (32.0f * sL[tid]);
    __syncthreads();

    {
        const size_t obase = (size_t)(b * E_ + h * D_ + lrow) * W_ + n0;
#pragma unroll
        for (int u = 0; u < 4; u++) {
            int col = lcb + u * 4;
            float4 v = *(const float4*)(&sS[lrow * 132 + col]);
            v.x *= sM[col]; v.y *= sM[col + 1]; v.z *= sM[col + 2]; v.w *= sM[col + 3];
            uint2 uh, ul;
            split4(v, uh, ul);
            *(uint2*)(g_o_hi + obase + col) = uh;
            *(uint2*)(g_o_lo + obase + col) = ul;
        }
    }
}

// ---------------------------------------------------------------------------
extern "C" void kernel_launch(void* const* d_in, const int* in_sizes, int n_in,
                              void* d_out, int out_size)
{
    const float* x  = (const float*)d_in[0];
    const float* LQ = (const float*)d_in[1];
    const float* LK = (const float*)d_in[2];
    const float* LV = (const float*)d_in[3];
    const float* Mw = (const float*)d_in[4];
    const float* bv = (const float*)d_in[5];
    float* out = (float*)d_out;

    cudaFuncSetAttribute(k_proj_mma,   cudaFuncAttributeMaxDynamicSharedMemorySize, SMEM_MMA);
    cudaFuncSetAttribute(k_final_mma,  cudaFuncAttributeMaxDynamicSharedMemorySize, SMEM_MMA);
    cudaFuncSetAttribute(k_attn_fused, cudaFuncAttributeMaxDynamicSharedMemorySize, SMEM_FZ);

    dim3 blk(256);

    k_split_all<<<16384, blk>>>(LQ, LK, LV, Mw, x);

    k_proj_mma  <<<dim3(8, 8, 12), blk, SMEM_MMA>>>();
    k_attn_fused<<<dim3(8, 64),    512, SMEM_FZ>>>();
    k_final_mma <<<dim3(8, 8, 4),  blk, SMEM_MMA>>>(bv, out);
}